// round 7
// baseline (speedup 1.0000x reference)
#include <cuda_runtime.h>
#include <cstdint>

#define CC 64
#define HWN 262144
#define NB 256
#define FINE 131072            // 2^17 fine bins per channel (lambda ~ 1)
#define TILEB 2048
#define NT (FINE / TILEB)      // 64 tiles per channel
#define NTP (NT + 1)           // + channel total
#define LUTN 2048
#define NBLK ((HWN / 8 / 256) * CC)   // k_loss total blocks = 8192

// ---------------- scratch ----------------------------------------------------------
__device__ int           g_nI, g_nJ;
__device__ int           g_minJ[CC];     // float bits (values >= 0 -> int order == float order)
__device__ int           g_maxJ[CC];
__device__ int           g_histJ[CC * NB];
__device__ float         g_hisJf[CC * NB];
__device__ float         g_cumJ[CC * NB];
__device__ float         g_minJf[CC];
__device__ float         g_stepf[CC];
__device__ int           g_cnt[CC * FINE];   // counts -> (in place) tile-local offsets -> rank cursors
__device__ int           g_tbase[CC * NTP];  // per-tile channel base + channel total
__device__ unsigned char g_lut[CC * LUTN];   // rank-cell -> starting coarse bin
__device__ float         g_lutinv;
__device__ double        g_loss;
__device__ unsigned int  g_done;

static __device__ __forceinline__ int fbin(float x) {
    int b = (int)(x * (float)FINE);
    return b < 0 ? 0 : (b > FINE - 1 ? FINE - 1 : b);
}

// ---------------- K0: init ----------------------------------------------------------
__global__ void k_init() {
    int i = blockIdx.x * blockDim.x + threadIdx.x;
    if (i < CC * FINE / 4) ((int4*)g_cnt)[i] = make_int4(0, 0, 0, 0);
    if (i < CC * NB) g_histJ[i] = 0;
    if (i < CC) { g_minJ[i] = 0x7F800000; g_maxJ[i] = 0; }
    if (i == 0) { g_nI = 0; g_nJ = 0; g_loss = 0.0; g_done = 0u; }
}

// ---------------- K1: fused fine-count(I) + minmax(J) + mask sums --------------------
__global__ void k_pass1(const float4* __restrict__ I, const float4* __restrict__ J,
                        const int4* __restrict__ mI4, const int4* __restrict__ mJ4) {
    int c = blockIdx.y;
    int i = blockIdx.x * blockDim.x + threadIdx.x;     // HWN/8 per channel
    int base = c * (HWN / 4) + i * 2;

    float4 i0 = I[base], i1 = I[base + 1];
    int4  mi0 = mI4[i * 2], mi1 = mI4[i * 2 + 1];
    float4 j0 = J[base], j1 = J[base + 1];
    int4  mj0 = mJ4[i * 2], mj1 = mJ4[i * 2 + 1];

    int* cnt = g_cnt + c * FINE;
    #define FC(mm, vv) if (mm) atomicAdd(&cnt[fbin(vv)], 1);
    FC(mi0.x, i0.x) FC(mi0.y, i0.y) FC(mi0.z, i0.z) FC(mi0.w, i0.w)
    FC(mi1.x, i1.x) FC(mi1.y, i1.y) FC(mi1.z, i1.z) FC(mi1.w, i1.w)
    #undef FC

    float mn = 1e30f, mx = -1e30f;
    if (mj0.x) { mn = fminf(mn, j0.x); mx = fmaxf(mx, j0.x); }
    if (mj0.y) { mn = fminf(mn, j0.y); mx = fmaxf(mx, j0.y); }
    if (mj0.z) { mn = fminf(mn, j0.z); mx = fmaxf(mx, j0.z); }
    if (mj0.w) { mn = fminf(mn, j0.w); mx = fmaxf(mx, j0.w); }
    if (mj1.x) { mn = fminf(mn, j1.x); mx = fmaxf(mx, j1.x); }
    if (mj1.y) { mn = fminf(mn, j1.y); mx = fmaxf(mx, j1.y); }
    if (mj1.z) { mn = fminf(mn, j1.z); mx = fmaxf(mx, j1.z); }
    if (mj1.w) { mn = fminf(mn, j1.w); mx = fmaxf(mx, j1.w); }

    if (c == 0) {
        int sI = mi0.x + mi0.y + mi0.z + mi0.w + mi1.x + mi1.y + mi1.z + mi1.w;
        int sJ = mj0.x + mj0.y + mj0.z + mj0.w + mj1.x + mj1.y + mj1.z + mj1.w;
        for (int o = 16; o; o >>= 1) {
            sI += __shfl_down_sync(0xFFFFFFFFu, sI, o);
            sJ += __shfl_down_sync(0xFFFFFFFFu, sJ, o);
        }
        if ((threadIdx.x & 31) == 0) { atomicAdd(&g_nI, sI); atomicAdd(&g_nJ, sJ); }
    }

    for (int o = 16; o; o >>= 1) {
        mn = fminf(mn, __shfl_down_sync(0xFFFFFFFFu, mn, o));
        mx = fmaxf(mx, __shfl_down_sync(0xFFFFFFFFu, mx, o));
    }
    __shared__ float smn[8], smx[8];
    int t = threadIdx.x;
    if ((t & 31) == 0) { smn[t >> 5] = mn; smx[t >> 5] = mx; }
    __syncthreads();
    if (t < 8) {
        mn = smn[t]; mx = smx[t];
        for (int o = 4; o; o >>= 1) {
            mn = fminf(mn, __shfl_down_sync(0xFFu, mn, o));
            mx = fmaxf(mx, __shfl_down_sync(0xFFu, mx, o));
        }
        if (t == 0) {
            if (mn < 1e30f)  atomicMin(&g_minJ[c], __float_as_int(mn));
            if (mx > -1e30f) atomicMax(&g_maxJ[c], __float_as_int(mx));
        }
    }
}

// ---------------- K2: 256-bin masked histogram of J (4-replica shared) --------------
__global__ void k_histJ(const float4* __restrict__ J, const int4* __restrict__ mJ4) {
    __shared__ int sh[4 * NB];
    int c = blockIdx.y;
    int t = threadIdx.x;
    #pragma unroll
    for (int k = 0; k < 4; k++) sh[k * NB + t] = 0;
    __syncthreads();
    float minf = __int_as_float(g_minJ[c]);
    float maxf = __int_as_float(g_maxJ[c]);
    float step = (maxf - minf) * (1.0f / NB);
    float sden = fmaxf(step, 1e-12f);
    int i = blockIdx.x * blockDim.x + t;
    int base = c * (HWN / 4) + i * 2;
    float4 v0 = J[base], v1 = J[base + 1];
    int4  m0 = mJ4[i * 2], m1 = mJ4[i * 2 + 1];
    int* h = sh + (t & 3) * NB;
    #define HADD(mm, vv) if (mm) { int b = (int)floorf((vv - minf) / sden); b = max(0, min(NB - 1, b)); atomicAdd(&h[b], 1); }
    HADD(m0.x, v0.x) HADD(m0.y, v0.y) HADD(m0.z, v0.z) HADD(m0.w, v0.w)
    HADD(m1.x, v1.x) HADD(m1.y, v1.y) HADD(m1.z, v1.z) HADD(m1.w, v1.w)
    #undef HADD
    __syncthreads();
    int s = sh[t] + sh[NB + t] + sh[2 * NB + t] + sh[3 * NB + t];
    if (s) atomicAdd(&g_histJ[c * NB + t], s);
}

// ---------------- K3a: per-tile in-place exclusive scan (int4, 8 bins/thread) --------
__global__ void k_scanA() {
    int c = blockIdx.y, tile = blockIdx.x, t = threadIdx.x;   // 256 threads, 2048 bins
    int base = c * FINE + tile * TILEB + t * 8;
    int4 a = *(const int4*)&g_cnt[base];
    int4 b = *(const int4*)&g_cnt[base + 4];
    int v[8] = {a.x, a.y, a.z, a.w, b.x, b.y, b.z, b.w};
    int loc[8];
    int run = 0;
    #pragma unroll
    for (int k = 0; k < 8; k++) { loc[k] = run; run += v[k]; }
    int lane = t & 31, wid = t >> 5;
    int x = run;
    for (int o = 1; o < 32; o <<= 1) {
        int u = __shfl_up_sync(0xFFFFFFFFu, x, o);
        if (lane >= o) x += u;
    }
    __shared__ int wsum[8];
    if (lane == 31) wsum[wid] = x;
    __syncthreads();
    if (t < 8) {
        int y = wsum[t];
        for (int o = 1; o < 8; o <<= 1) {
            int u = __shfl_up_sync(0xFFu, y, o);
            if (t >= o) y += u;
        }
        wsum[t] = y;
    }
    __syncthreads();
    int ex = x - run + (wid ? wsum[wid - 1] : 0);
    *(int4*)&g_cnt[base]     = make_int4(ex + loc[0], ex + loc[1], ex + loc[2], ex + loc[3]);
    *(int4*)&g_cnt[base + 4] = make_int4(ex + loc[4], ex + loc[5], ex + loc[6], ex + loc[7]);
    if (t == 255) g_tbase[c * NTP + tile] = ex + run;   // tile total (made exclusive in scanB)
}

// ---------------- K3b: tile-base scan + CDF prep + rank LUT --------------------------
__global__ void k_scanB() {
    int c = blockIdx.x, t = threadIdx.x;   // 256 threads
    if (t < 32) {
        // each lane owns tiles 2t, 2t+1 — warp-only, no block barriers here
        int v0 = g_tbase[c * NTP + 2 * t];
        int v1 = g_tbase[c * NTP + 2 * t + 1];
        int sum = v0 + v1;
        int incl = sum;
        for (int o = 1; o < 32; o <<= 1) {
            int u = __shfl_up_sync(0xFFFFFFFFu, incl, o);
            if (t >= o) incl += u;
        }
        int ex = incl - sum;               // exclusive base of tile 2t
        g_tbase[c * NTP + 2 * t] = ex;
        g_tbase[c * NTP + 2 * t + 1] = ex + v0;
        if (t == 31) g_tbase[c * NTP + NT] = incl;   // channel total
    }
    // CDF prep: scale + 256-wide parallel scan (remap continuous at bin edges)
    __shared__ float sh[NB];
    float scale = (float)g_nI / (float)g_nJ;
    float h = (float)g_histJ[c * NB + t] * scale;
    g_hisJf[c * NB + t] = h;
    sh[t] = h;
    __syncthreads();
    for (int o = 1; o < NB; o <<= 1) {
        float add = (t >= o) ? sh[t - o] : 0.0f;
        __syncthreads();
        sh[t] += add;
        __syncthreads();
    }
    g_cumJ[c * NB + t] = sh[t];
    if (t == 0) {
        float minf = __int_as_float(g_minJ[c]);
        float maxf = __int_as_float(g_maxJ[c]);
        g_minJf[c] = minf;
        g_stepf[c] = (maxf - minf) * (1.0f / NB);
    }
    // rank->bin LUT: cell k starts at rank k*cellw + 1
    int cellw = (g_nI + LUTN - 1) / LUTN;
    if (c == 0 && t == 0) g_lutinv = 1.0f / (float)cellw;
    #pragma unroll
    for (int k = 0; k < LUTN / NB; k++) {
        int cell = t * (LUTN / NB) + k;
        float r0 = (float)(cell * cellw + 1);
        int pos = 0;
        #pragma unroll
        for (int st = 128; st > 0; st >>= 1) {
            int np = pos + st;
            if (np <= NB && sh[np - 1] < r0) pos = np;
        }
        g_lut[c * LUTN + cell] = (unsigned char)(pos > NB - 1 ? NB - 1 : pos);
    }
}

// ---------------- K4: rank-assign + CDF-inverse + loss + fused finalize --------------
__global__ void k_loss(const float4* __restrict__ I, const int4* __restrict__ mI4,
                       float* __restrict__ out) {
    int c = blockIdx.y;
    int t = threadIdx.x;
    __shared__ float scum[NB], shis[NB];
    __shared__ unsigned char slut[LUTN];
    __shared__ int stb[NTP];
    scum[t] = g_cumJ[c * NB + t];
    shis[t] = g_hisJf[c * NB + t];
    ((uint64_t*)slut)[t] = ((const uint64_t*)&g_lut[c * LUTN])[t];   // 8 bytes/thread
    if (t < NTP) stb[t] = g_tbase[c * NTP + t];
    __syncthreads();
    float minf = g_minJf[c], step = g_stepf[c];
    float lutinv = g_lutinv;
    int ctot = stb[NT];
    int i = blockIdx.x * blockDim.x + t;
    int base = c * (HWN / 4) + i * 2;
    float4 v0 = I[base], v1 = I[base + 1];
    int4  m0 = mI4[i * 2], m1 = mI4[i * 2 + 1];
    int* off = g_cnt + c * FINE;

    double acc = 0.0;
    #define DO(mm, vv) if (mm) {                                                   \
        int b = fbin(vv);                                                          \
        int tb0 = stb[b >> 11];                                                    \
        int cur = off[b];                                                          \
        int nxt = (b == FINE - 1) ? ctot : (stb[(b + 1) >> 11] + off[b + 1]);      \
        int gb = tb0 + cur;                                                        \
        int p;                                                                     \
        if (nxt - gb == 1) p = gb;               /* provably last unclaimed */     \
        else               p = tb0 + atomicAdd(&off[b], 1);                        \
        float r = (float)(p + 1);                                                  \
        int idx = (int)((r - 1.0f) * lutinv);                                      \
        idx = idx < 0 ? 0 : (idx > LUTN - 1 ? LUTN - 1 : idx);                     \
        int bi = slut[idx];                                                        \
        while (bi < NB - 1 && scum[bi] < r) bi++;                                  \
        while (bi > 0 && scum[bi - 1] >= r) bi--;                                  \
        float cJ = scum[bi], hb = shis[bi];                                        \
        float ratio = (r - (cJ - hb)) / fmaxf(hb, 1e-12f);                         \
        ratio = fminf(fmaxf(ratio, 0.0f), 1.0f);                                   \
        float f = minf + ((float)bi + ratio) * step;                               \
        float d = vv - f;                                                          \
        acc += (double)d * (double)d;                                              \
    }
    DO(m0.x, v0.x) DO(m0.y, v0.y) DO(m0.z, v0.z) DO(m0.w, v0.w)
    DO(m1.x, v1.x) DO(m1.y, v1.y) DO(m1.z, v1.z) DO(m1.w, v1.w)
    #undef DO

    for (int o = 16; o; o >>= 1) acc += __shfl_down_sync(0xFFFFFFFFu, acc, o);
    __shared__ double sacc[8];
    if ((t & 31) == 0) sacc[t >> 5] = acc;
    __syncthreads();
    if (t < 8) {
        double a = sacc[t];
        for (int o = 4; o; o >>= 1) a += __shfl_down_sync(0xFFu, a, o);
        if (t == 0) {
            atomicAdd(&g_loss, a);
            __threadfence();
            unsigned int ticket = atomicAdd(&g_done, 1u);
            if (ticket == NBLK - 1) {
                double tot = atomicAdd(&g_loss, 0.0);    // read through L2
                out[0] = (float)(tot * (100.0 / ((double)CC * (double)HWN)));
            }
        }
    }
}

extern "C" void kernel_launch(void* const* d_in, const int* in_sizes, int n_in,
                              void* d_out, int out_size) {
    const float* I = (const float*)d_in[0];
    const float* J = (const float*)d_in[1];
    const int*  mI = (const int*)d_in[2];
    const int*  mJ = (const int*)d_in[3];
    float* out = (float*)d_out;

    static cudaStream_t s_aux = nullptr;
    static cudaEvent_t  s_fork = nullptr, s_join = nullptr;
    if (!s_aux) {
        cudaStreamCreateWithFlags(&s_aux, cudaStreamNonBlocking);
        cudaEventCreateWithFlags(&s_fork, cudaEventDisableTiming);
        cudaEventCreateWithFlags(&s_join, cudaEventDisableTiming);
    }

    k_init<<<(CC * FINE / 4) / 1024, 1024>>>();

    dim3 g8((HWN / 8) / 256, CC);   // 128 x 64, 8 elems/thread
    k_pass1<<<g8, 256>>>((const float4*)I, (const float4*)J, (const int4*)mI, (const int4*)mJ);

    // fork: histJ on aux stream, scanA on main stream (independent)
    cudaEventRecord(s_fork, 0);
    cudaStreamWaitEvent(s_aux, s_fork, 0);
    k_histJ<<<g8, 256, 0, s_aux>>>((const float4*)J, (const int4*)mJ);
    cudaEventRecord(s_join, s_aux);

    dim3 gs(NT, CC);                // 64 x 64
    k_scanA<<<gs, 256>>>();

    cudaStreamWaitEvent(0, s_join, 0);
    k_scanB<<<CC, NB>>>();

    k_loss<<<g8, 256>>>((const float4*)I, (const int4*)mI, out);
}

// round 8
// speedup vs baseline: 1.1063x; 1.1063x over previous
#include <cuda_runtime.h>
#include <cstdint>

#define CC 64
#define HWN 262144
#define NB 256
#define FINE 32768             // 2^15 fine bins per channel (lambda ~ 4)
#define TILEB 2048
#define NT (FINE / TILEB)      // 16 tiles per channel
#define NTP (NT + 1)           // + channel total
#define NBLK ((HWN / 8 / 256) * CC)   // k_loss total blocks = 8192

// ---------------- scratch ----------------------------------------------------------
__device__ int           g_nI, g_nJ;
__device__ int           g_minJ[CC];     // float bits (values >= 0 -> int order == float order)
__device__ int           g_maxJ[CC];
__device__ int           g_histJ[CC * NB];
__device__ float         g_hisJf[CC * NB];
__device__ float         g_cumJ[CC * NB];
__device__ float         g_minJf[CC];
__device__ float         g_stepf[CC];
__device__ int           g_cnt[CC * FINE];   // counts -> (in place) tile-local offsets -> rank cursors
__device__ int           g_tbase[CC * NTP];  // per-tile channel base (+ channel total)
__device__ double        g_loss;
__device__ unsigned int  g_done;

static __device__ __forceinline__ int fbin(float x) {
    int b = (int)(x * (float)FINE);
    return b < 0 ? 0 : (b > FINE - 1 ? FINE - 1 : b);
}

// ---------------- K0: init ----------------------------------------------------------
__global__ void k_init() {
    int i = blockIdx.x * blockDim.x + threadIdx.x;
    ((int4*)g_cnt)[i] = make_int4(0, 0, 0, 0);          // CC*FINE/4 threads
    if (i < CC * NB) g_histJ[i] = 0;
    if (i < CC) { g_minJ[i] = 0x7F800000; g_maxJ[i] = 0; }
    if (i == 0) { g_nI = 0; g_nJ = 0; g_loss = 0.0; g_done = 0u; }
}

// ---------------- K1: fused fine-count(I) + minmax(J) + mask sums --------------------
__global__ void k_pass1(const float4* __restrict__ I, const float4* __restrict__ J,
                        const int4* __restrict__ mI4, const int4* __restrict__ mJ4) {
    int c = blockIdx.y;
    int i = blockIdx.x * blockDim.x + threadIdx.x;     // HWN/8 per channel
    int base = c * (HWN / 4) + i * 2;

    float4 i0 = I[base], i1 = I[base + 1];
    int4  mi0 = mI4[i * 2], mi1 = mI4[i * 2 + 1];
    float4 j0 = J[base], j1 = J[base + 1];
    int4  mj0 = mJ4[i * 2], mj1 = mJ4[i * 2 + 1];

    int* cnt = g_cnt + c * FINE;
    #define FC(mm, vv) if (mm) atomicAdd(&cnt[fbin(vv)], 1);
    FC(mi0.x, i0.x) FC(mi0.y, i0.y) FC(mi0.z, i0.z) FC(mi0.w, i0.w)
    FC(mi1.x, i1.x) FC(mi1.y, i1.y) FC(mi1.z, i1.z) FC(mi1.w, i1.w)
    #undef FC

    float mn = 1e30f, mx = -1e30f;
    if (mj0.x) { mn = fminf(mn, j0.x); mx = fmaxf(mx, j0.x); }
    if (mj0.y) { mn = fminf(mn, j0.y); mx = fmaxf(mx, j0.y); }
    if (mj0.z) { mn = fminf(mn, j0.z); mx = fmaxf(mx, j0.z); }
    if (mj0.w) { mn = fminf(mn, j0.w); mx = fmaxf(mx, j0.w); }
    if (mj1.x) { mn = fminf(mn, j1.x); mx = fmaxf(mx, j1.x); }
    if (mj1.y) { mn = fminf(mn, j1.y); mx = fmaxf(mx, j1.y); }
    if (mj1.z) { mn = fminf(mn, j1.z); mx = fmaxf(mx, j1.z); }
    if (mj1.w) { mn = fminf(mn, j1.w); mx = fmaxf(mx, j1.w); }

    if (c == 0) {
        int sI = mi0.x + mi0.y + mi0.z + mi0.w + mi1.x + mi1.y + mi1.z + mi1.w;
        int sJ = mj0.x + mj0.y + mj0.z + mj0.w + mj1.x + mj1.y + mj1.z + mj1.w;
        for (int o = 16; o; o >>= 1) {
            sI += __shfl_down_sync(0xFFFFFFFFu, sI, o);
            sJ += __shfl_down_sync(0xFFFFFFFFu, sJ, o);
        }
        if ((threadIdx.x & 31) == 0) { atomicAdd(&g_nI, sI); atomicAdd(&g_nJ, sJ); }
    }

    for (int o = 16; o; o >>= 1) {
        mn = fminf(mn, __shfl_down_sync(0xFFFFFFFFu, mn, o));
        mx = fmaxf(mx, __shfl_down_sync(0xFFFFFFFFu, mx, o));
    }
    __shared__ float smn[8], smx[8];
    int t = threadIdx.x;
    if ((t & 31) == 0) { smn[t >> 5] = mn; smx[t >> 5] = mx; }
    __syncthreads();
    if (t < 8) {
        mn = smn[t]; mx = smx[t];
        for (int o = 4; o; o >>= 1) {
            mn = fminf(mn, __shfl_down_sync(0xFFu, mn, o));
            mx = fmaxf(mx, __shfl_down_sync(0xFFu, mx, o));
        }
        if (t == 0) {
            if (mn < 1e30f)  atomicMin(&g_minJ[c], __float_as_int(mn));
            if (mx > -1e30f) atomicMax(&g_maxJ[c], __float_as_int(mx));
        }
    }
}

// ---------------- K2: 256-bin masked histogram of J (4-replica shared) --------------
__global__ void k_histJ(const float4* __restrict__ J, const int4* __restrict__ mJ4) {
    __shared__ int sh[4 * NB];
    int c = blockIdx.y;
    int t = threadIdx.x;
    #pragma unroll
    for (int k = 0; k < 4; k++) sh[k * NB + t] = 0;
    __syncthreads();
    float minf = __int_as_float(g_minJ[c]);
    float maxf = __int_as_float(g_maxJ[c]);
    float step = (maxf - minf) * (1.0f / NB);
    float sden = fmaxf(step, 1e-12f);
    int i = blockIdx.x * blockDim.x + t;
    int base = c * (HWN / 4) + i * 2;
    float4 v0 = J[base], v1 = J[base + 1];
    int4  m0 = mJ4[i * 2], m1 = mJ4[i * 2 + 1];
    int* h = sh + (t & 3) * NB;
    #define HADD(mm, vv) if (mm) { int b = (int)floorf((vv - minf) / sden); b = max(0, min(NB - 1, b)); atomicAdd(&h[b], 1); }
    HADD(m0.x, v0.x) HADD(m0.y, v0.y) HADD(m0.z, v0.z) HADD(m0.w, v0.w)
    HADD(m1.x, v1.x) HADD(m1.y, v1.y) HADD(m1.z, v1.z) HADD(m1.w, v1.w)
    #undef HADD
    __syncthreads();
    int s = sh[t] + sh[NB + t] + sh[2 * NB + t] + sh[3 * NB + t];
    if (s) atomicAdd(&g_histJ[c * NB + t], s);
}

// ---------------- K3a: per-tile in-place exclusive scan (int4, 8 bins/thread) --------
__global__ void k_scanA() {
    int c = blockIdx.y, tile = blockIdx.x, t = threadIdx.x;   // 256 threads, 2048 bins
    int base = c * FINE + tile * TILEB + t * 8;
    int4 a = *(const int4*)&g_cnt[base];
    int4 b = *(const int4*)&g_cnt[base + 4];
    int v[8] = {a.x, a.y, a.z, a.w, b.x, b.y, b.z, b.w};
    int loc[8];
    int run = 0;
    #pragma unroll
    for (int k = 0; k < 8; k++) { loc[k] = run; run += v[k]; }
    int lane = t & 31, wid = t >> 5;
    int x = run;
    for (int o = 1; o < 32; o <<= 1) {
        int u = __shfl_up_sync(0xFFFFFFFFu, x, o);
        if (lane >= o) x += u;
    }
    __shared__ int wsum[8];
    if (lane == 31) wsum[wid] = x;
    __syncthreads();
    if (t < 8) {
        int y = wsum[t];
        for (int o = 1; o < 8; o <<= 1) {
            int u = __shfl_up_sync(0xFFu, y, o);
            if (t >= o) y += u;
        }
        wsum[t] = y;
    }
    __syncthreads();
    int ex = x - run + (wid ? wsum[wid - 1] : 0);
    *(int4*)&g_cnt[base]     = make_int4(ex + loc[0], ex + loc[1], ex + loc[2], ex + loc[3]);
    *(int4*)&g_cnt[base + 4] = make_int4(ex + loc[4], ex + loc[5], ex + loc[6], ex + loc[7]);
    if (t == 255) g_tbase[c * NTP + tile] = ex + run;   // tile total (made exclusive in scanB)
}

// ---------------- K3b: tile-base scan (warp 0, 16 lanes) + CDF prep ------------------
__global__ void k_scanB() {
    int c = blockIdx.x, t = threadIdx.x;   // 256 threads
    if (t < NT) {
        int v = g_tbase[c * NTP + t];
        int incl = v;
        for (int o = 1; o < NT; o <<= 1) {
            int u = __shfl_up_sync(0xFFFFu, incl, o);
            if (t >= o) incl += u;
        }
        g_tbase[c * NTP + t] = incl - v;     // exclusive base
        if (t == NT - 1) g_tbase[c * NTP + NT] = incl;   // channel total
    }
    // CDF prep: scale + 256-wide parallel scan (remap continuous at bin edges)
    __shared__ float sh[NB];
    float scale = (float)g_nI / (float)g_nJ;
    float h = (float)g_histJ[c * NB + t] * scale;
    g_hisJf[c * NB + t] = h;
    sh[t] = h;
    __syncthreads();
    for (int o = 1; o < NB; o <<= 1) {
        float add = (t >= o) ? sh[t - o] : 0.0f;
        __syncthreads();
        sh[t] += add;
        __syncthreads();
    }
    g_cumJ[c * NB + t] = sh[t];
    if (t == 0) {
        float minf = __int_as_float(g_minJ[c]);
        float maxf = __int_as_float(g_maxJ[c]);
        g_minJf[c] = minf;
        g_stepf[c] = (maxf - minf) * (1.0f / NB);
    }
}

// ---------------- K4: rank-assign + CDF-inverse + loss + fused finalize --------------
__global__ void k_loss(const float4* __restrict__ I, const int4* __restrict__ mI4,
                       float* __restrict__ out) {
    int c = blockIdx.y;
    int t = threadIdx.x;
    __shared__ float scum[NB], shis[NB];
    __shared__ int stb[NT];
    scum[t] = g_cumJ[c * NB + t];
    shis[t] = g_hisJf[c * NB + t];
    if (t < NT) stb[t] = g_tbase[c * NTP + t];
    __syncthreads();
    float minf = g_minJf[c], step = g_stepf[c];
    int i = blockIdx.x * blockDim.x + t;
    int base = c * (HWN / 4) + i * 2;
    float4 v0 = I[base], v1 = I[base + 1];
    int4  m0 = mI4[i * 2], m1 = mI4[i * 2 + 1];
    int* off = g_cnt + c * FINE;

    double acc = 0.0;
    #define DO(mm, vv) if (mm) {                                                   \
        int b = fbin(vv);                                                          \
        int p = atomicAdd(&off[b], 1);                                             \
        float r = (float)(stb[b >> 11] + p + 1);                                   \
        int pos = 0;                                                               \
        _Pragma("unroll")                                                          \
        for (int st = 128; st > 0; st >>= 1) {                                     \
            int np = pos + st;                                                     \
            if (np <= NB && scum[np - 1] < r) pos = np;                            \
        }                                                                          \
        int bi = pos > NB - 1 ? NB - 1 : pos;                                      \
        float cJ = scum[bi], hb = shis[bi];                                        \
        float ratio = (r - (cJ - hb)) / fmaxf(hb, 1e-12f);                         \
        ratio = fminf(fmaxf(ratio, 0.0f), 1.0f);                                   \
        float f = minf + ((float)bi + ratio) * step;                               \
        float d = vv - f;                                                          \
        acc += (double)d * (double)d;                                              \
    }
    DO(m0.x, v0.x) DO(m0.y, v0.y) DO(m0.z, v0.z) DO(m0.w, v0.w)
    DO(m1.x, v1.x) DO(m1.y, v1.y) DO(m1.z, v1.z) DO(m1.w, v1.w)
    #undef DO

    for (int o = 16; o; o >>= 1) acc += __shfl_down_sync(0xFFFFFFFFu, acc, o);
    __shared__ double sacc[8];
    if ((t & 31) == 0) sacc[t >> 5] = acc;
    __syncthreads();
    if (t < 8) {
        double a = sacc[t];
        for (int o = 4; o; o >>= 1) a += __shfl_down_sync(0xFFu, a, o);
        if (t == 0) {
            atomicAdd(&g_loss, a);
            __threadfence();
            unsigned int ticket = atomicAdd(&g_done, 1u);
            if (ticket == NBLK - 1) {
                double tot = atomicAdd(&g_loss, 0.0);    // read through L2
                out[0] = (float)(tot * (100.0 / ((double)CC * (double)HWN)));
            }
        }
    }
}

extern "C" void kernel_launch(void* const* d_in, const int* in_sizes, int n_in,
                              void* d_out, int out_size) {
    const float* I = (const float*)d_in[0];
    const float* J = (const float*)d_in[1];
    const int*  mI = (const int*)d_in[2];
    const int*  mJ = (const int*)d_in[3];
    float* out = (float*)d_out;

    k_init<<<(CC * FINE / 4) / 1024, 1024>>>();

    dim3 g8((HWN / 8) / 256, CC);   // 128 x 64, 8 elems/thread
    k_pass1<<<g8, 256>>>((const float4*)I, (const float4*)J, (const int4*)mI, (const int4*)mJ);

    k_histJ<<<g8, 256>>>((const float4*)J, (const int4*)mJ);

    dim3 gs(NT, CC);                // 16 x 64
    k_scanA<<<gs, 256>>>();
    k_scanB<<<CC, NB>>>();

    k_loss<<<g8, 256>>>((const float4*)I, (const int4*)mI, out);
}

// round 9
// speedup vs baseline: 1.1388x; 1.0294x over previous
#include <cuda_runtime.h>
#include <cstdint>

#define CC 64
#define HWN 262144
#define NB 256
#define FINE 32768             // 2^15 fine bins per channel (lambda ~ 4)
#define WBIN (1.0f / (float)FINE)
#define TILEB 2048
#define NT (FINE / TILEB)      // 16 tiles per channel
#define NTP (NT + 1)
#define NBLK ((HWN / 8 / 256) * CC)   // k_loss total blocks = 8192

// ---------------- scratch ----------------------------------------------------------
__device__ int            g_nI, g_nJ;
__device__ int            g_minJ[CC];    // float bits (values >= 0 -> int order == float order)
__device__ int            g_maxJ[CC];
__device__ int            g_histJ[CC * NB];
__device__ float          g_hisJf[CC * NB];
__device__ float          g_cumJ[CC * NB];
__device__ float          g_minJf[CC];
__device__ float          g_stepf[CC];
__device__ int            g_cnt[CC * FINE];      // counts -> offsets -> rank cursors (8MB, L2-hot)
__device__ int            g_tbase[CC * NTP];
__device__ unsigned short g_qI[CC * HWN];        // fine-bin id of I, 0xFFFF = unmasked (32MB)
__device__ unsigned short g_qJ[CC * HWN];        // fine-bin id of J, 0xFFFF = unmasked (32MB)
__device__ double         g_loss;
__device__ unsigned int   g_done;

static __device__ __forceinline__ int fbin(float x) {
    int b = (int)(x * (float)FINE);
    return b < 0 ? 0 : (b > FINE - 1 ? FINE - 1 : b);
}

// ---------------- K0: init ----------------------------------------------------------
__global__ void k_init() {
    int i = blockIdx.x * blockDim.x + threadIdx.x;
    ((int4*)g_cnt)[i] = make_int4(0, 0, 0, 0);          // CC*FINE/4 threads
    if (i < CC * NB) g_histJ[i] = 0;
    if (i < CC) { g_minJ[i] = 0x7F800000; g_maxJ[i] = 0; }
    if (i == 0) { g_nI = 0; g_nJ = 0; g_loss = 0.0; g_done = 0u; }
}

// ---------------- K1: read I,J once: count(I), quantize I&J, minmax(J), mask sums ----
__global__ void k_pass1(const float4* __restrict__ I, const float4* __restrict__ J,
                        const int4* __restrict__ mI4, const int4* __restrict__ mJ4) {
    int c = blockIdx.y;
    int i = blockIdx.x * blockDim.x + threadIdx.x;     // HWN/8 per channel
    int base = c * (HWN / 4) + i * 2;

    float4 i0 = I[base], i1 = I[base + 1];
    int4  mi0 = mI4[i * 2], mi1 = mI4[i * 2 + 1];
    float4 j0 = J[base], j1 = J[base + 1];
    int4  mj0 = mJ4[i * 2], mj1 = mJ4[i * 2 + 1];

    // --- quantize I to fine-bin ids (0xFFFF = unmasked) + count masked I ---
    int* cnt = g_cnt + c * FINE;
    unsigned short qi[8], qj[8];
    {
        float vi[8] = {i0.x, i0.y, i0.z, i0.w, i1.x, i1.y, i1.z, i1.w};
        int   mi[8] = {mi0.x, mi0.y, mi0.z, mi0.w, mi1.x, mi1.y, mi1.z, mi1.w};
        float vj[8] = {j0.x, j0.y, j0.z, j0.w, j1.x, j1.y, j1.z, j1.w};
        int   mj[8] = {mj0.x, mj0.y, mj0.z, mj0.w, mj1.x, mj1.y, mj1.z, mj1.w};
        #pragma unroll
        for (int k = 0; k < 8; k++) {
            int bi = fbin(vi[k]);
            qi[k] = mi[k] ? (unsigned short)bi : (unsigned short)0xFFFF;
            if (mi[k]) atomicAdd(&cnt[bi], 1);
            qj[k] = mj[k] ? (unsigned short)fbin(vj[k]) : (unsigned short)0xFFFF;
        }
    }
    size_t pix = (size_t)c * HWN + (size_t)i * 8;
    *(uint4*)&g_qI[pix] = *(const uint4*)qi;
    *(uint4*)&g_qJ[pix] = *(const uint4*)qj;

    // --- masked min/max of J (exact values) ---
    float mn = 1e30f, mx = -1e30f;
    if (mj0.x) { mn = fminf(mn, j0.x); mx = fmaxf(mx, j0.x); }
    if (mj0.y) { mn = fminf(mn, j0.y); mx = fmaxf(mx, j0.y); }
    if (mj0.z) { mn = fminf(mn, j0.z); mx = fmaxf(mx, j0.z); }
    if (mj0.w) { mn = fminf(mn, j0.w); mx = fmaxf(mx, j0.w); }
    if (mj1.x) { mn = fminf(mn, j1.x); mx = fmaxf(mx, j1.x); }
    if (mj1.y) { mn = fminf(mn, j1.y); mx = fmaxf(mx, j1.y); }
    if (mj1.z) { mn = fminf(mn, j1.z); mx = fmaxf(mx, j1.z); }
    if (mj1.w) { mn = fminf(mn, j1.w); mx = fmaxf(mx, j1.w); }

    if (c == 0) {
        int sI = mi0.x + mi0.y + mi0.z + mi0.w + mi1.x + mi1.y + mi1.z + mi1.w;
        int sJ = mj0.x + mj0.y + mj0.z + mj0.w + mj1.x + mj1.y + mj1.z + mj1.w;
        for (int o = 16; o; o >>= 1) {
            sI += __shfl_down_sync(0xFFFFFFFFu, sI, o);
            sJ += __shfl_down_sync(0xFFFFFFFFu, sJ, o);
        }
        if ((threadIdx.x & 31) == 0) { atomicAdd(&g_nI, sI); atomicAdd(&g_nJ, sJ); }
    }

    for (int o = 16; o; o >>= 1) {
        mn = fminf(mn, __shfl_down_sync(0xFFFFFFFFu, mn, o));
        mx = fmaxf(mx, __shfl_down_sync(0xFFFFFFFFu, mx, o));
    }
    __shared__ float smn[8], smx[8];
    int t = threadIdx.x;
    if ((t & 31) == 0) { smn[t >> 5] = mn; smx[t >> 5] = mx; }
    __syncthreads();
    if (t < 8) {
        mn = smn[t]; mx = smx[t];
        for (int o = 4; o; o >>= 1) {
            mn = fminf(mn, __shfl_down_sync(0xFFu, mn, o));
            mx = fmaxf(mx, __shfl_down_sync(0xFFu, mx, o));
        }
        if (t == 0) {
            if (mn < 1e30f)  atomicMin(&g_minJ[c], __float_as_int(mn));
            if (mx > -1e30f) atomicMax(&g_maxJ[c], __float_as_int(mx));
        }
    }
}

// ---------------- K2: 256-bin histogram of J from u16 ids (4-replica shared) --------
__global__ void k_histJ() {
    __shared__ int sh[4 * NB];
    int c = blockIdx.y;
    int t = threadIdx.x;
    #pragma unroll
    for (int k = 0; k < 4; k++) sh[k * NB + t] = 0;
    __syncthreads();
    float minf = __int_as_float(g_minJ[c]);
    float maxf = __int_as_float(g_maxJ[c]);
    float step = (maxf - minf) * (1.0f / NB);
    float sden = fmaxf(step, 1e-12f);
    int i = blockIdx.x * blockDim.x + t;
    size_t pix = (size_t)c * HWN + (size_t)i * 8;
    uint4 q = *(const uint4*)&g_qJ[pix];
    unsigned short id[8];
    *(uint4*)id = q;
    int* h = sh + (t & 3) * NB;
    #pragma unroll
    for (int k = 0; k < 8; k++) {
        if (id[k] != 0xFFFF) {
            float v = ((float)id[k] + 0.5f) * WBIN;      // fine-bin center approximation
            int b = (int)floorf((v - minf) / sden);
            b = max(0, min(NB - 1, b));
            atomicAdd(&h[b], 1);
        }
    }
    __syncthreads();
    int s = sh[t] + sh[NB + t] + sh[2 * NB + t] + sh[3 * NB + t];
    if (s) atomicAdd(&g_histJ[c * NB + t], s);
}

// ---------------- K3a: per-tile in-place exclusive scan (int4, 8 bins/thread) --------
__global__ void k_scanA() {
    int c = blockIdx.y, tile = blockIdx.x, t = threadIdx.x;   // 256 threads, 2048 bins
    int base = c * FINE + tile * TILEB + t * 8;
    int4 a = *(const int4*)&g_cnt[base];
    int4 b = *(const int4*)&g_cnt[base + 4];
    int v[8] = {a.x, a.y, a.z, a.w, b.x, b.y, b.z, b.w};
    int loc[8];
    int run = 0;
    #pragma unroll
    for (int k = 0; k < 8; k++) { loc[k] = run; run += v[k]; }
    int lane = t & 31, wid = t >> 5;
    int x = run;
    for (int o = 1; o < 32; o <<= 1) {
        int u = __shfl_up_sync(0xFFFFFFFFu, x, o);
        if (lane >= o) x += u;
    }
    __shared__ int wsum[8];
    if (lane == 31) wsum[wid] = x;
    __syncthreads();
    if (t < 8) {
        int y = wsum[t];
        for (int o = 1; o < 8; o <<= 1) {
            int u = __shfl_up_sync(0xFFu, y, o);
            if (t >= o) y += u;
        }
        wsum[t] = y;
    }
    __syncthreads();
    int ex = x - run + (wid ? wsum[wid - 1] : 0);
    *(int4*)&g_cnt[base]     = make_int4(ex + loc[0], ex + loc[1], ex + loc[2], ex + loc[3]);
    *(int4*)&g_cnt[base + 4] = make_int4(ex + loc[4], ex + loc[5], ex + loc[6], ex + loc[7]);
    if (t == 255) g_tbase[c * NTP + tile] = ex + run;
}

// ---------------- K3b: tile-base scan (warp 0) + CDF prep ----------------------------
__global__ void k_scanB() {
    int c = blockIdx.x, t = threadIdx.x;   // 256 threads
    if (t < NT) {
        int v = g_tbase[c * NTP + t];
        int incl = v;
        for (int o = 1; o < NT; o <<= 1) {
            int u = __shfl_up_sync(0xFFFFu, incl, o);
            if (t >= o) incl += u;
        }
        g_tbase[c * NTP + t] = incl - v;
        if (t == NT - 1) g_tbase[c * NTP + NT] = incl;
    }
    __shared__ float sh[NB];
    float scale = (float)g_nI / (float)g_nJ;
    float h = (float)g_histJ[c * NB + t] * scale;
    g_hisJf[c * NB + t] = h;
    sh[t] = h;
    __syncthreads();
    for (int o = 1; o < NB; o <<= 1) {
        float add = (t >= o) ? sh[t - o] : 0.0f;
        __syncthreads();
        sh[t] += add;
        __syncthreads();
    }
    g_cumJ[c * NB + t] = sh[t];
    if (t == 0) {
        float minf = __int_as_float(g_minJ[c]);
        float maxf = __int_as_float(g_maxJ[c]);
        g_minJf[c] = minf;
        g_stepf[c] = (maxf - minf) * (1.0f / NB);
    }
}

// ---------------- K4: rank-assign + CDF-inverse + loss from u16 ids ------------------
__global__ void k_loss(float* __restrict__ out) {
    int c = blockIdx.y;
    int t = threadIdx.x;
    __shared__ float scum[NB], shis[NB];
    __shared__ int stb[NT];
    scum[t] = g_cumJ[c * NB + t];
    shis[t] = g_hisJf[c * NB + t];
    if (t < NT) stb[t] = g_tbase[c * NTP + t];
    __syncthreads();
    float minf = g_minJf[c], step = g_stepf[c];
    int i = blockIdx.x * blockDim.x + t;
    size_t pix = (size_t)c * HWN + (size_t)i * 8;
    uint4 q = *(const uint4*)&g_qI[pix];
    unsigned short id[8];
    *(uint4*)id = q;
    int* off = g_cnt + c * FINE;

    double acc = 0.0;
    #pragma unroll
    for (int k = 0; k < 8; k++) {
        if (id[k] != 0xFFFF) {
            int b = (int)id[k];
            int p = atomicAdd(&off[b], 1);
            float r = (float)(stb[b >> 11] + p + 1);
            int pos = 0;
            #pragma unroll
            for (int st = 128; st > 0; st >>= 1) {
                int np = pos + st;
                if (np <= NB && scum[np - 1] < r) pos = np;
            }
            int bi = pos > NB - 1 ? NB - 1 : pos;
            float cJ = scum[bi], hb = shis[bi];
            float ratio = (r - (cJ - hb)) / fmaxf(hb, 1e-12f);
            ratio = fminf(fmaxf(ratio, 0.0f), 1.0f);
            float f = minf + ((float)bi + ratio) * step;
            float x = ((float)b + 0.5f) * WBIN;          // fine-bin center approximation
            float d = x - f;
            acc += (double)d * (double)d;
        }
    }

    for (int o = 16; o; o >>= 1) acc += __shfl_down_sync(0xFFFFFFFFu, acc, o);
    __shared__ double sacc[8];
    if ((t & 31) == 0) sacc[t >> 5] = acc;
    __syncthreads();
    if (t < 8) {
        double a = sacc[t];
        for (int o = 4; o; o >>= 1) a += __shfl_down_sync(0xFFu, a, o);
        if (t == 0) {
            atomicAdd(&g_loss, a);
            __threadfence();
            unsigned int ticket = atomicAdd(&g_done, 1u);
            if (ticket == NBLK - 1) {
                double tot = atomicAdd(&g_loss, 0.0);
                out[0] = (float)(tot * (100.0 / ((double)CC * (double)HWN)));
            }
        }
    }
}

extern "C" void kernel_launch(void* const* d_in, const int* in_sizes, int n_in,
                              void* d_out, int out_size) {
    const float* I = (const float*)d_in[0];
    const float* J = (const float*)d_in[1];
    const int*  mI = (const int*)d_in[2];
    const int*  mJ = (const int*)d_in[3];
    float* out = (float*)d_out;

    k_init<<<(CC * FINE / 4) / 1024, 1024>>>();

    dim3 g8((HWN / 8) / 256, CC);   // 128 x 64, 8 elems/thread
    k_pass1<<<g8, 256>>>((const float4*)I, (const float4*)J, (const int4*)mI, (const int4*)mJ);

    k_histJ<<<g8, 256>>>();

    dim3 gs(NT, CC);                // 16 x 64
    k_scanA<<<gs, 256>>>();
    k_scanB<<<CC, NB>>>();

    k_loss<<<g8, 256>>>(out);
}

// round 10
// speedup vs baseline: 1.2989x; 1.1406x over previous
#include <cuda_runtime.h>
#include <cstdint>

#define CC 64
#define HWN 262144
#define NB 256
#define FINE 32768             // 2^15 fine bins per channel (lambda ~ 4)
#define WBIN (1.0f / (float)FINE)
#define TILEB 2048
#define NT (FINE / TILEB)      // 16 tiles per channel
#define NTP (NT + 1)
#define NBLK (CC * NT)         // k_loss blocks = 1024

// ---------------- scratch ----------------------------------------------------------
__device__ int            g_nI, g_nJ;
__device__ int            g_minJ[CC];    // float bits (values >= 0 -> int order == float order)
__device__ int            g_maxJ[CC];
__device__ int            g_histJ[CC * NB];
__device__ float          g_hisJf[CC * NB];
__device__ float          g_cumJ[CC * NB];
__device__ float          g_minJf[CC];
__device__ float          g_stepf[CC];
__device__ int            g_cnt[CC * FINE];      // counts -> (in place) tile-local offsets (8MB)
__device__ int            g_tbase[CC * NTP];
__device__ unsigned short g_qJ[CC * HWN];        // fine-bin id of J, 0xFFFF = unmasked (32MB)
__device__ double         g_loss;
__device__ unsigned int   g_done;

static __device__ __forceinline__ int fbin(float x) {
    int b = (int)(x * (float)FINE);
    return b < 0 ? 0 : (b > FINE - 1 ? FINE - 1 : b);
}

// ---------------- K0: init ----------------------------------------------------------
__global__ void k_init() {
    int i = blockIdx.x * blockDim.x + threadIdx.x;
    ((int4*)g_cnt)[i] = make_int4(0, 0, 0, 0);          // CC*FINE/4 threads
    if (i < CC * NB) g_histJ[i] = 0;
    if (i < CC) { g_minJ[i] = 0x7F800000; g_maxJ[i] = 0; }
    if (i == 0) { g_nI = 0; g_nJ = 0; g_loss = 0.0; g_done = 0u; }
}

// ---------------- K1: read I,J once: count(I), quantize J, minmax(J), mask sums ------
__global__ void k_pass1(const float4* __restrict__ I, const float4* __restrict__ J,
                        const int4* __restrict__ mI4, const int4* __restrict__ mJ4) {
    int c = blockIdx.y;
    int i = blockIdx.x * blockDim.x + threadIdx.x;     // HWN/8 per channel
    int base = c * (HWN / 4) + i * 2;

    float4 i0 = I[base], i1 = I[base + 1];
    int4  mi0 = mI4[i * 2], mi1 = mI4[i * 2 + 1];
    float4 j0 = J[base], j1 = J[base + 1];
    int4  mj0 = mJ4[i * 2], mj1 = mJ4[i * 2 + 1];

    // --- count masked I into fine bins; quantize J to u16 ids ---
    int* cnt = g_cnt + c * FINE;
    unsigned short qj[8];
    {
        float vi[8] = {i0.x, i0.y, i0.z, i0.w, i1.x, i1.y, i1.z, i1.w};
        int   mi[8] = {mi0.x, mi0.y, mi0.z, mi0.w, mi1.x, mi1.y, mi1.z, mi1.w};
        float vj[8] = {j0.x, j0.y, j0.z, j0.w, j1.x, j1.y, j1.z, j1.w};
        int   mj[8] = {mj0.x, mj0.y, mj0.z, mj0.w, mj1.x, mj1.y, mj1.z, mj1.w};
        #pragma unroll
        for (int k = 0; k < 8; k++) {
            if (mi[k]) atomicAdd(&cnt[fbin(vi[k])], 1);
            qj[k] = mj[k] ? (unsigned short)fbin(vj[k]) : (unsigned short)0xFFFF;
        }
    }
    *(uint4*)&g_qJ[(size_t)c * HWN + (size_t)i * 8] = *(const uint4*)qj;

    // --- masked min/max of J (exact values) ---
    float mn = 1e30f, mx = -1e30f;
    if (mj0.x) { mn = fminf(mn, j0.x); mx = fmaxf(mx, j0.x); }
    if (mj0.y) { mn = fminf(mn, j0.y); mx = fmaxf(mx, j0.y); }
    if (mj0.z) { mn = fminf(mn, j0.z); mx = fmaxf(mx, j0.z); }
    if (mj0.w) { mn = fminf(mn, j0.w); mx = fmaxf(mx, j0.w); }
    if (mj1.x) { mn = fminf(mn, j1.x); mx = fmaxf(mx, j1.x); }
    if (mj1.y) { mn = fminf(mn, j1.y); mx = fmaxf(mx, j1.y); }
    if (mj1.z) { mn = fminf(mn, j1.z); mx = fmaxf(mx, j1.z); }
    if (mj1.w) { mn = fminf(mn, j1.w); mx = fmaxf(mx, j1.w); }

    if (c == 0) {
        int sI = mi0.x + mi0.y + mi0.z + mi0.w + mi1.x + mi1.y + mi1.z + mi1.w;
        int sJ = mj0.x + mj0.y + mj0.z + mj0.w + mj1.x + mj1.y + mj1.z + mj1.w;
        for (int o = 16; o; o >>= 1) {
            sI += __shfl_down_sync(0xFFFFFFFFu, sI, o);
            sJ += __shfl_down_sync(0xFFFFFFFFu, sJ, o);
        }
        if ((threadIdx.x & 31) == 0) { atomicAdd(&g_nI, sI); atomicAdd(&g_nJ, sJ); }
    }

    for (int o = 16; o; o >>= 1) {
        mn = fminf(mn, __shfl_down_sync(0xFFFFFFFFu, mn, o));
        mx = fmaxf(mx, __shfl_down_sync(0xFFFFFFFFu, mx, o));
    }
    __shared__ float smn[8], smx[8];
    int t = threadIdx.x;
    if ((t & 31) == 0) { smn[t >> 5] = mn; smx[t >> 5] = mx; }
    __syncthreads();
    if (t < 8) {
        mn = smn[t]; mx = smx[t];
        for (int o = 4; o; o >>= 1) {
            mn = fminf(mn, __shfl_down_sync(0xFFu, mn, o));
            mx = fmaxf(mx, __shfl_down_sync(0xFFu, mx, o));
        }
        if (t == 0) {
            if (mn < 1e30f)  atomicMin(&g_minJ[c], __float_as_int(mn));
            if (mx > -1e30f) atomicMax(&g_maxJ[c], __float_as_int(mx));
        }
    }
}

// ---------------- K2: 256-bin histogram of J from u16 ids (4-replica shared) --------
__global__ void k_histJ() {
    __shared__ int sh[4 * NB];
    int c = blockIdx.y;
    int t = threadIdx.x;
    #pragma unroll
    for (int k = 0; k < 4; k++) sh[k * NB + t] = 0;
    __syncthreads();
    float minf = __int_as_float(g_minJ[c]);
    float maxf = __int_as_float(g_maxJ[c]);
    float step = (maxf - minf) * (1.0f / NB);
    float sden = fmaxf(step, 1e-12f);
    int i = blockIdx.x * blockDim.x + t;
    uint4 q = *(const uint4*)&g_qJ[(size_t)c * HWN + (size_t)i * 8];
    unsigned short id[8];
    *(uint4*)id = q;
    int* h = sh + (t & 3) * NB;
    #pragma unroll
    for (int k = 0; k < 8; k++) {
        if (id[k] != 0xFFFF) {
            float v = ((float)id[k] + 0.5f) * WBIN;      // fine-bin center approximation
            int b = (int)floorf((v - minf) / sden);
            b = max(0, min(NB - 1, b));
            atomicAdd(&h[b], 1);
        }
    }
    __syncthreads();
    int s = sh[t] + sh[NB + t] + sh[2 * NB + t] + sh[3 * NB + t];
    if (s) atomicAdd(&g_histJ[c * NB + t], s);
}

// ---------------- K3a: per-tile in-place exclusive scan (int4, 8 bins/thread) --------
__global__ void k_scanA() {
    int c = blockIdx.y, tile = blockIdx.x, t = threadIdx.x;   // 256 threads, 2048 bins
    int base = c * FINE + tile * TILEB + t * 8;
    int4 a = *(const int4*)&g_cnt[base];
    int4 b = *(const int4*)&g_cnt[base + 4];
    int v[8] = {a.x, a.y, a.z, a.w, b.x, b.y, b.z, b.w};
    int loc[8];
    int run = 0;
    #pragma unroll
    for (int k = 0; k < 8; k++) { loc[k] = run; run += v[k]; }
    int lane = t & 31, wid = t >> 5;
    int x = run;
    for (int o = 1; o < 32; o <<= 1) {
        int u = __shfl_up_sync(0xFFFFFFFFu, x, o);
        if (lane >= o) x += u;
    }
    __shared__ int wsum[8];
    if (lane == 31) wsum[wid] = x;
    __syncthreads();
    if (t < 8) {
        int y = wsum[t];
        for (int o = 1; o < 8; o <<= 1) {
            int u = __shfl_up_sync(0xFFu, y, o);
            if (t >= o) y += u;
        }
        wsum[t] = y;
    }
    __syncthreads();
    int ex = x - run + (wid ? wsum[wid - 1] : 0);
    *(int4*)&g_cnt[base]     = make_int4(ex + loc[0], ex + loc[1], ex + loc[2], ex + loc[3]);
    *(int4*)&g_cnt[base + 4] = make_int4(ex + loc[4], ex + loc[5], ex + loc[6], ex + loc[7]);
    if (t == 255) g_tbase[c * NTP + tile] = ex + run;
}

// ---------------- K3b: tile-base scan (warp 0) + CDF prep ----------------------------
__global__ void k_scanB() {
    int c = blockIdx.x, t = threadIdx.x;   // 256 threads
    if (t < NT) {
        int v = g_tbase[c * NTP + t];
        int incl = v;
        for (int o = 1; o < NT; o <<= 1) {
            int u = __shfl_up_sync(0xFFFFu, incl, o);
            if (t >= o) incl += u;
        }
        g_tbase[c * NTP + t] = incl - v;
        if (t == NT - 1) g_tbase[c * NTP + NT] = incl;   // channel total
    }
    __shared__ float sh[NB];
    float scale = (float)g_nI / (float)g_nJ;
    float h = (float)g_histJ[c * NB + t] * scale;
    g_hisJf[c * NB + t] = h;
    sh[t] = h;
    __syncthreads();
    for (int o = 1; o < NB; o <<= 1) {
        float add = (t >= o) ? sh[t - o] : 0.0f;
        __syncthreads();
        sh[t] += add;
        __syncthreads();
    }
    g_cumJ[c * NB + t] = sh[t];
    if (t == 0) {
        float minf = __int_as_float(g_minJ[c]);
        float maxf = __int_as_float(g_maxJ[c]);
        g_minJf[c] = minf;
        g_stepf[c] = (maxf - minf) * (1.0f / NB);
    }
}

// ---------------- K4: per-bin analytic loss (no atomics, no pixel reads) -------------
// All pixels in fine bin b share x = bin center and occupy ranks s+1..s+m exactly.
__global__ void k_loss(float* __restrict__ out) {
    int c = blockIdx.y, tile = blockIdx.x, t = threadIdx.x;   // 256 threads, 8 bins each
    __shared__ float scum[NB], shis[NB];
    __shared__ int stb[NTP];
    scum[t] = g_cumJ[c * NB + t];
    shis[t] = g_hisJf[c * NB + t];
    if (t < NTP) stb[t] = g_tbase[c * NTP + t];
    __syncthreads();
    float minf = g_minJf[c], step = g_stepf[c];

    int base = c * FINE + tile * TILEB + t * 8;
    int4 a = *(const int4*)&g_cnt[base];
    int4 bq = *(const int4*)&g_cnt[base + 4];
    int o9[9] = {a.x, a.y, a.z, a.w, bq.x, bq.y, bq.z, bq.w, 0};
    int tb = stb[tile];
    if (t < 255) o9[8] = g_cnt[base + 8];               // next group's first offset (same tile)
    int e_thread_last = (t < 255) ? (tb + o9[8]) : stb[tile + 1];   // stb[NT] = channel total

    double acc = 0.0;
    int bi = 0;
    bool first = true;
    #pragma unroll
    for (int k = 0; k < 8; k++) {
        int s = tb + o9[k];
        int e = (k < 7) ? (tb + o9[k + 1]) : e_thread_last;
        if (e <= s) continue;
        float xb = ((float)(tile * TILEB + t * 8 + k) + 0.5f) * WBIN;  // bin center
        for (int p = s; p < e; p++) {
            float r = (float)(p + 1);
            if (first) {                                 // one binary search per thread
                int pos = 0;
                #pragma unroll
                for (int st = 128; st > 0; st >>= 1) {
                    int np = pos + st;
                    if (np <= NB && scum[np - 1] < r) pos = np;
                }
                bi = pos > NB - 1 ? NB - 1 : pos;
                first = false;
            } else {                                     // ranks monotone -> advance pointer
                while (bi < NB - 1 && scum[bi] < r) bi++;
            }
            float cJ = scum[bi], hb = shis[bi];
            float ratio = (r - (cJ - hb)) / fmaxf(hb, 1e-12f);
            ratio = fminf(fmaxf(ratio, 0.0f), 1.0f);
            float f = minf + ((float)bi + ratio) * step;
            float d = xb - f;
            acc += (double)d * (double)d;
        }
    }

    for (int o = 16; o; o >>= 1) acc += __shfl_down_sync(0xFFFFFFFFu, acc, o);
    __shared__ double sacc[8];
    if ((t & 31) == 0) sacc[t >> 5] = acc;
    __syncthreads();
    if (t < 8) {
        double v = sacc[t];
        for (int o = 4; o; o >>= 1) v += __shfl_down_sync(0xFFu, v, o);
        if (t == 0) {
            atomicAdd(&g_loss, v);
            __threadfence();
            unsigned int ticket = atomicAdd(&g_done, 1u);
            if (ticket == NBLK - 1) {
                double tot = atomicAdd(&g_loss, 0.0);
                out[0] = (float)(tot * (100.0 / ((double)CC * (double)HWN)));
            }
        }
    }
}

extern "C" void kernel_launch(void* const* d_in, const int* in_sizes, int n_in,
                              void* d_out, int out_size) {
    const float* I = (const float*)d_in[0];
    const float* J = (const float*)d_in[1];
    const int*  mI = (const int*)d_in[2];
    const int*  mJ = (const int*)d_in[3];
    float* out = (float*)d_out;

    k_init<<<(CC * FINE / 4) / 1024, 1024>>>();

    dim3 g8((HWN / 8) / 256, CC);   // 128 x 64, 8 elems/thread
    k_pass1<<<g8, 256>>>((const float4*)I, (const float4*)J, (const int4*)mI, (const int4*)mJ);

    k_histJ<<<g8, 256>>>();

    dim3 gs(NT, CC);                // 16 x 64
    k_scanA<<<gs, 256>>>();
    k_scanB<<<CC, NB>>>();

    k_loss<<<gs, 256>>>(out);
}